// round 3
// baseline (speedup 1.0000x reference)
#include <cuda_runtime.h>
#include <cstdint>

#define NPTS      1048576
#define TABLE_SZ  1048577
#define FEAT_DIM  8
#define NLEVELS   3

__global__ __launch_bounds__(256) void feature_octree_kernel(
    const float* __restrict__ coord,      // (N, 3)
    const float* __restrict__ features,   // (3, TABLE, 8)
    const int*   __restrict__ indices,    // (3, N, 8)
    float*       __restrict__ out)        // (N, 8)
{
    int n = blockIdx.x * blockDim.x + threadIdx.x;
    if (n >= NPTS) return;

    const float x = coord[3 * n + 0];
    const float y = coord[3 * n + 1];
    const float z = coord[3 * n + 2];

    // Front-batch ALL index loads (3 levels x 8 corners) for max MLP.
    int4 iv[NLEVELS][2];
#pragma unroll
    for (int i = 0; i < NLEVELS; ++i) {
        const int4* __restrict__ idxp =
            (const int4*)(indices + ((size_t)i * NPTS + (size_t)n) * 8);
        iv[i][0] = __ldg(idxp + 0);
        iv[i][1] = __ldg(idxp + 1);
    }

    float acc0 = 0.f, acc1 = 0.f, acc2 = 0.f, acc3 = 0.f;
    float acc4 = 0.f, acc5 = 0.f, acc6 = 0.f, acc7 = 0.f;

    // level i: current_level = 12 - i -> scale = 2^(12-i); feature_level = 2 - i
    const float scales[NLEVELS] = {4096.0f, 2048.0f, 1024.0f};

#pragma unroll
    for (int i = 0; i < NLEVELS; ++i) {
        const float s = scales[i] * 0.5f;
        float cx = fmaf(s, x, s);
        float cy = fmaf(s, y, s);
        float cz = fmaf(s, z, s);
        float tx = cx - floorf(cx);
        float ty = cy - floorf(cy);
        float tz = cz - floorf(cz);
        // smoothstep polynomial
        tx = tx * tx * (3.0f - 2.0f * tx);
        ty = ty * ty * (3.0f - 2.0f * ty);
        tz = tz * tz * (3.0f - 2.0f * tz);

        const float wx[2] = {1.0f - tx, tx};
        const float wy[2] = {1.0f - ty, ty};
        const float wz[2] = {1.0f - tz, tz};

        const float* __restrict__ ftab =
            features + (size_t)(NLEVELS - 1 - i) * (size_t)TABLE_SZ * FEAT_DIM;

        const int idx8[8] = {iv[i][0].x, iv[i][0].y, iv[i][0].z, iv[i][0].w,
                             iv[i][1].x, iv[i][1].y, iv[i][1].z, iv[i][1].w};

#pragma unroll
        for (int c = 0; c < 8; ++c) {
            const int id = idx8[c];
            float w = wx[(c >> 2) & 1] * wy[(c >> 1) & 1] * wz[c & 1];
            // reference zeroes the last table row
            if (id == TABLE_SZ - 1) w = 0.0f;

            const float4* __restrict__ g = (const float4*)(ftab + (size_t)id * FEAT_DIM);
            const float4 g0 = __ldg(g + 0);
            const float4 g1 = __ldg(g + 1);

            acc0 = fmaf(w, g0.x, acc0);
            acc1 = fmaf(w, g0.y, acc1);
            acc2 = fmaf(w, g0.z, acc2);
            acc3 = fmaf(w, g0.w, acc3);
            acc4 = fmaf(w, g1.x, acc4);
            acc5 = fmaf(w, g1.y, acc5);
            acc6 = fmaf(w, g1.z, acc6);
            acc7 = fmaf(w, g1.w, acc7);
        }
    }

    float4* __restrict__ o = (float4*)(out + (size_t)n * FEAT_DIM);
    o[0] = make_float4(acc0, acc1, acc2, acc3);
    o[1] = make_float4(acc4, acc5, acc6, acc7);
}

extern "C" void kernel_launch(void* const* d_in, const int* in_sizes, int n_in,
                              void* d_out, int out_size)
{
    const float* coord    = (const float*)d_in[0];
    const float* features = (const float*)d_in[1];
    const int*   indices  = (const int*)d_in[2];
    float*       out      = (float*)d_out;

    const int threads = 256;
    const int blocks = (NPTS + threads - 1) / threads;
    feature_octree_kernel<<<blocks, threads>>>(coord, features, indices, out);
}

// round 4
// speedup vs baseline: 1.3577x; 1.3577x over previous
#include <cuda_runtime.h>
#include <cstdint>

#define NPTS      1048576
#define TABLE_SZ  1048577
#define FEAT_DIM  8
#define NLEVELS   3

// One pass per octree level. 2 threads per point: lane half h=0 handles
// feats 0-3, h=1 handles feats 4-7. The pair's two 16B gather loads hit the
// same 128B line -> 1 L1tex wavefront per corner entry instead of 2.
template <int LEVEL>
__global__ __launch_bounds__(256) void octree_pass_kernel(
    const float* __restrict__ coord,     // (N, 3)
    const float* __restrict__ ftab,      // (TABLE, 8) for this level's table
    const int*   __restrict__ idx,       // (N, 8) for this level
    float*       __restrict__ out)       // (N, 8)
{
    const int t = blockIdx.x * blockDim.x + threadIdx.x;
    const int n = t >> 1;       // point id
    const int h = t & 1;        // feature half (0: feats 0-3, 1: feats 4-7)
    if (n >= NPTS) return;

    // current_level = 12 - LEVEL -> grid scale 2^(12-LEVEL)
    const float s = (float)(1 << (12 - LEVEL)) * 0.5f;

    const float x = coord[3 * n + 0];
    const float y = coord[3 * n + 1];
    const float z = coord[3 * n + 2];

    float cx = fmaf(s, x, s);
    float cy = fmaf(s, y, s);
    float cz = fmaf(s, z, s);
    float tx = cx - floorf(cx);
    float ty = cy - floorf(cy);
    float tz = cz - floorf(cz);
    // smoothstep polynomial
    tx = tx * tx * (3.0f - 2.0f * tx);
    ty = ty * ty * (3.0f - 2.0f * ty);
    tz = tz * tz * (3.0f - 2.0f * tz);

    const float wx[2] = {1.0f - tx, tx};
    const float wy[2] = {1.0f - ty, ty};
    const float wz[2] = {1.0f - tz, tz};

    // Both lanes of the pair load the same 32B of indices (broadcast in L1).
    const int4* __restrict__ idxp = (const int4*)(idx + (size_t)n * 8);
    const int4 iA = __ldg(idxp + 0);
    const int4 iB = __ldg(idxp + 1);
    const int idx8[8] = {iA.x, iA.y, iA.z, iA.w, iB.x, iB.y, iB.z, iB.w};

    float a0 = 0.f, a1 = 0.f, a2 = 0.f, a3 = 0.f;

#pragma unroll
    for (int c = 0; c < 8; ++c) {
        const int id = idx8[c];
        float w = wx[(c >> 2) & 1] * wy[(c >> 1) & 1] * wz[c & 1];
        // reference zeroes the last table row
        if (id == TABLE_SZ - 1) w = 0.0f;

        const float4 g = __ldg((const float4*)(ftab + (size_t)id * FEAT_DIM) + h);
        a0 = fmaf(w, g.x, a0);
        a1 = fmaf(w, g.y, a1);
        a2 = fmaf(w, g.z, a2);
        a3 = fmaf(w, g.w, a3);
    }

    float4* __restrict__ o = (float4*)(out + (size_t)n * FEAT_DIM) + h;
    if (LEVEL == 0) {
        *o = make_float4(a0, a1, a2, a3);
    } else {
        float4 prev = *o;
        *o = make_float4(prev.x + a0, prev.y + a1, prev.z + a2, prev.w + a3);
    }
}

extern "C" void kernel_launch(void* const* d_in, const int* in_sizes, int n_in,
                              void* d_out, int out_size)
{
    const float* coord    = (const float*)d_in[0];
    const float* features = (const float*)d_in[1];   // (3, TABLE, 8)
    const int*   indices  = (const int*)d_in[2];     // (3, N, 8)
    float*       out      = (float*)d_out;

    const size_t table_elems = (size_t)TABLE_SZ * FEAT_DIM;
    const size_t idx_elems   = (size_t)NPTS * 8;

    const int threads = 256;
    const int blocks = (2 * NPTS + threads - 1) / threads;

    // Pass i uses feature table (NLEVELS-1-i) and indices slice i.
    octree_pass_kernel<0><<<blocks, threads>>>(
        coord, features + 2 * table_elems, indices + 0 * idx_elems, out);
    octree_pass_kernel<1><<<blocks, threads>>>(
        coord, features + 1 * table_elems, indices + 1 * idx_elems, out);
    octree_pass_kernel<2><<<blocks, threads>>>(
        coord, features + 0 * table_elems, indices + 2 * idx_elems, out);
}